// round 6
// baseline (speedup 1.0000x reference)
#include <cuda_runtime.h>
#include <cuda_bf16.h>
#include <stdint.h>

// Problem constants (fixed dataset: GraphConvSparse)
#define MAX_NODES 100000
#define MAX_EDGES 3200000
#define IN_DIM    512
#define OUT_DIM   128

// ---------------- scratch (static device globals; no cudaMalloc allowed) ----
__device__ float4 g_xp4[MAX_NODES * (OUT_DIM / 4)];   // projected features [N,128], 51.2 MB
__device__ int    g_rowptr[MAX_NODES + 1];
__device__ int    g_cursor[MAX_NODES];
__device__ int    g_ecol[MAX_EDGES];
__device__ float  g_eval[MAX_EDGES];

// packed f32x2 helpers (sm_103a packed fp32 pipe; ptxas never auto-fuses these)
__device__ __forceinline__ unsigned long long pack2(float lo, float hi) {
    unsigned long long r;
    asm("mov.b64 %0, {%1, %2};" : "=l"(r) : "f"(lo), "f"(hi));
    return r;
}
__device__ __forceinline__ void unpack2(unsigned long long v, float& lo, float& hi) {
    asm("mov.b64 {%0, %1}, %2;" : "=f"(lo), "=f"(hi) : "l"(v));
}

// ---------------- CSR build ------------------------------------------------
__global__ void k_zero_deg(int n) {
    int i = blockIdx.x * blockDim.x + threadIdx.x;
    if (i < n) g_cursor[i] = 0;
}

__global__ void k_count(const int* __restrict__ erow, int E) {
    int e = blockIdx.x * blockDim.x + threadIdx.x;
    if (e < E) atomicAdd(&g_cursor[__ldcs(erow + e)], 1);
}

// single-block exclusive scan: g_cursor (degrees) -> g_rowptr
__global__ void k_scan(int n) {
    __shared__ int warpsums[32];
    __shared__ int s_running;
    __shared__ int s_total;
    int tid  = threadIdx.x;           // 1024 threads
    int lane = tid & 31;
    int wid  = tid >> 5;
    if (tid == 0) s_running = 0;
    __syncthreads();
    for (int base = 0; base < n; base += 1024) {
        int i = base + tid;
        int v = (i < n) ? g_cursor[i] : 0;
        int s = v;
        #pragma unroll
        for (int off = 1; off < 32; off <<= 1) {
            int t = __shfl_up_sync(0xffffffffu, s, off);
            if (lane >= off) s += t;
        }
        if (lane == 31) warpsums[wid] = s;
        __syncthreads();
        if (wid == 0) {
            int ws   = warpsums[lane];
            int incl = ws;
            #pragma unroll
            for (int off = 1; off < 32; off <<= 1) {
                int t = __shfl_up_sync(0xffffffffu, incl, off);
                if (lane >= off) incl += t;
            }
            warpsums[lane] = incl - ws;          // exclusive prefix of warp sums
            if (lane == 31) s_total = incl;      // chunk total
        }
        __syncthreads();
        int excl = (s - v) + warpsums[wid] + s_running;
        if (i < n) g_rowptr[i] = excl;
        __syncthreads();
        if (tid == 0) s_running += s_total;
        __syncthreads();
    }
    if (tid == 0) g_rowptr[n] = s_running;
}

__global__ void k_init_cursor(int n) {
    int i = blockIdx.x * blockDim.x + threadIdx.x;
    if (i < n) g_cursor[i] = g_rowptr[i];
}

__global__ void k_scatter(const int* __restrict__ erow, const int* __restrict__ ecol,
                          const float* __restrict__ eval, int E) {
    int e = blockIdx.x * blockDim.x + threadIdx.x;
    if (e < E) {
        int r = erow[e];
        int p = atomicAdd(&g_cursor[r], 1);
        g_ecol[p] = ecol[e];
        g_eval[p] = eval[e];
    }
}

// ---------------- dense GEMM: xp = x @ W ------------------------------------
// 128x128 tile, KT=16, 8x8 per thread, double-buffered smem, f32x2 packed FMA.
// X global reads use streaming (.cs) hints: read-once data must not evict the
// xp results (needed L2-resident for the aggregation phase).
#define KT 16
__global__ __launch_bounds__(256, 2)
void k_gemm(const float* __restrict__ X, const float* __restrict__ W, int N) {
    __shared__ float As[2][KT][128];   // [buf][k][m]
    __shared__ float Bs[2][KT][128];   // [buf][k][n]
    float* XP = (float*)g_xp4;

    int tid = threadIdx.x;
    int blockRow = blockIdx.x * 128;
    int ty = tid >> 4;        // 0..15
    int tx = tid & 15;        // 0..15

    // per-thread global-load coordinates (fixed across K slabs)
    int arow0 = (tid >> 2);            // X rows: arow0 and arow0+64
    int acol  = (tid & 3) * 4;         // X cols within slab
    int wkk0  = tid >> 5;              // W rows tid>>5 and tid>>5 + 8
    int wkk1  = (tid >> 5) + 8;
    int wnc   = (tid & 31) * 4;

    // accumulator: 8 rows x 4 f32x2 pairs (= 8x8 fp32)
    unsigned long long acc2[8][4];
    #pragma unroll
    for (int i = 0; i < 8; ++i)
        #pragma unroll
        for (int j = 0; j < 4; ++j) acc2[i][j] = 0ull;

    float4 xa, xb, wa, wb;

    // ---- load slab 0 into registers ----
    {
        int gr0 = blockRow + arow0;
        int gr1 = blockRow + arow0 + 64;
        xa = make_float4(0.f,0.f,0.f,0.f);
        xb = make_float4(0.f,0.f,0.f,0.f);
        if (gr0 < N) xa = __ldcs((const float4*)(X + (size_t)gr0 * IN_DIM + acol));
        if (gr1 < N) xb = __ldcs((const float4*)(X + (size_t)gr1 * IN_DIM + acol));
        wa = *(const float4*)(W + (size_t)wkk0 * OUT_DIM + wnc);
        wb = *(const float4*)(W + (size_t)wkk1 * OUT_DIM + wnc);
    }
    // ---- store slab 0 into buffer 0 ----
    {
        As[0][acol+0][arow0] = xa.x; As[0][acol+1][arow0] = xa.y;
        As[0][acol+2][arow0] = xa.z; As[0][acol+3][arow0] = xa.w;
        As[0][acol+0][arow0+64] = xb.x; As[0][acol+1][arow0+64] = xb.y;
        As[0][acol+2][arow0+64] = xb.z; As[0][acol+3][arow0+64] = xb.w;
        *(float4*)&Bs[0][wkk0][wnc] = wa;
        *(float4*)&Bs[0][wkk1][wnc] = wb;
    }
    __syncthreads();

    int buf = 0;
    for (int k0 = KT; k0 <= IN_DIM; k0 += KT) {
        // prefetch next slab into registers (while computing current)
        if (k0 < IN_DIM) {
            int gr0 = blockRow + arow0;
            int gr1 = blockRow + arow0 + 64;
            xa = make_float4(0.f,0.f,0.f,0.f);
            xb = make_float4(0.f,0.f,0.f,0.f);
            if (gr0 < N) xa = __ldcs((const float4*)(X + (size_t)gr0 * IN_DIM + k0 + acol));
            if (gr1 < N) xb = __ldcs((const float4*)(X + (size_t)gr1 * IN_DIM + k0 + acol));
            wa = *(const float4*)(W + (size_t)(k0 + wkk0) * OUT_DIM + wnc);
            wb = *(const float4*)(W + (size_t)(k0 + wkk1) * OUT_DIM + wnc);
        }
        // compute on current buffer: packed f32x2 FMAs.
        // A fragment: 2x LDS.128; B fragment: 4x LDS.64 directly as packed pairs.
        #pragma unroll
        for (int kk = 0; kk < KT; ++kk) {
            float4 a0 = *(const float4*)&As[buf][kk][ty * 8];
            float4 a1 = *(const float4*)&As[buf][kk][ty * 8 + 4];
            unsigned long long b2[4];
            #pragma unroll
            for (int j = 0; j < 4; ++j)
                b2[j] = *(const unsigned long long*)&Bs[buf][kk][tx * 8 + 2 * j];
            float a[8] = {a0.x, a0.y, a0.z, a0.w, a1.x, a1.y, a1.z, a1.w};
            #pragma unroll
            for (int i = 0; i < 8; ++i) {
                unsigned long long aa = pack2(a[i], a[i]);
                #pragma unroll
                for (int j = 0; j < 4; ++j) {
                    asm("fma.rn.f32x2 %0, %1, %2, %0;"
                        : "+l"(acc2[i][j]) : "l"(aa), "l"(b2[j]));
                }
            }
        }
        // stage next slab into the other buffer
        if (k0 < IN_DIM) {
            int nb = buf ^ 1;
            As[nb][acol+0][arow0] = xa.x; As[nb][acol+1][arow0] = xa.y;
            As[nb][acol+2][arow0] = xa.z; As[nb][acol+3][arow0] = xa.w;
            As[nb][acol+0][arow0+64] = xb.x; As[nb][acol+1][arow0+64] = xb.y;
            As[nb][acol+2][arow0+64] = xb.z; As[nb][acol+3][arow0+64] = xb.w;
            *(float4*)&Bs[nb][wkk0][wnc] = wa;
            *(float4*)&Bs[nb][wkk1][wnc] = wb;
            __syncthreads();
        }
        buf ^= 1;
    }

    #pragma unroll
    for (int i = 0; i < 8; ++i) {
        int gr = blockRow + ty * 8 + i;
        if (gr < N) {
            #pragma unroll
            for (int j = 0; j < 8; j += 4) {
                float4 v;
                unpack2(acc2[i][j/2],     v.x, v.y);
                unpack2(acc2[i][j/2 + 1], v.z, v.w);
                *(float4*)(XP + (size_t)gr * OUT_DIM + tx * 8 + j) = v;
            }
        }
    }
}

// ---------------- aggregation: one warp per row, fused ReLU -----------------
// Depth-2 software pipeline; edge arrays read with streaming hints (read-once),
// output stored with streaming hints (write-once) so L2 stays owned by g_xp4.
__global__ __launch_bounds__(256)
void k_agg(float* __restrict__ out, int n) {
    int w    = (blockIdx.x * blockDim.x + threadIdx.x) >> 5;
    int lane = threadIdx.x & 31;
    if (w >= n) return;
    int s = g_rowptr[w];
    int e = g_rowptr[w + 1];
    float4 acc = make_float4(0.f, 0.f, 0.f, 0.f);
    const float4* __restrict__ xp4 = g_xp4;

    if (s < e) {
        int   c0 = __ldcs(g_ecol + s);
        float v0 = __ldcs(g_eval + s);
        float4 m0 = xp4[(size_t)c0 * 32 + lane];
        for (int i = s + 1; i < e; ++i) {
            int   c1 = __ldcs(g_ecol + i);
            float v1 = __ldcs(g_eval + i);
            float4 m1 = xp4[(size_t)c1 * 32 + lane];   // issue before consuming m0
            acc.x = fmaf(v0, m0.x, acc.x);
            acc.y = fmaf(v0, m0.y, acc.y);
            acc.z = fmaf(v0, m0.z, acc.z);
            acc.w = fmaf(v0, m0.w, acc.w);
            v0 = v1; m0 = m1;
        }
        acc.x = fmaf(v0, m0.x, acc.x);
        acc.y = fmaf(v0, m0.y, acc.y);
        acc.z = fmaf(v0, m0.z, acc.z);
        acc.w = fmaf(v0, m0.w, acc.w);
    }
    acc.x = fmaxf(acc.x, 0.f);
    acc.y = fmaxf(acc.y, 0.f);
    acc.z = fmaxf(acc.z, 0.f);
    acc.w = fmaxf(acc.w, 0.f);
    __stcs((float4*)out + (size_t)w * 32 + lane, acc);
}

// ---------------- launch ----------------------------------------------------
extern "C" void kernel_launch(void* const* d_in, const int* in_sizes, int n_in,
                              void* d_out, int out_size) {
    const float* x    = (const float*)d_in[0];
    const float* W    = (const float*)d_in[1];
    const int*   erow = (const int*)  d_in[2];
    const int*   ecol = (const int*)  d_in[3];
    const float* eval = (const float*)d_in[4];
    float* out = (float*)d_out;

    int N = in_sizes[0] / IN_DIM;   // 100000
    int E = in_sizes[2];            // 3200000

    int tb = 256;
    // CSR build
    k_zero_deg   <<<(N + tb - 1) / tb, tb>>>(N);
    k_count      <<<(E + tb - 1) / tb, tb>>>(erow, E);
    k_scan       <<<1, 1024>>>(N);
    k_init_cursor<<<(N + tb - 1) / tb, tb>>>(N);
    k_scatter    <<<(E + tb - 1) / tb, tb>>>(erow, ecol, eval, E);
    // dense projection
    k_gemm       <<<(N + 127) / 128, 256>>>(x, W, N);
    // per-row aggregation + ReLU
    k_agg        <<<(N * 32 + tb - 1) / tb, tb>>>(out, N);
}

// round 11
// speedup vs baseline: 1.4012x; 1.4012x over previous
#include <cuda_runtime.h>
#include <cuda_bf16.h>
#include <stdint.h>

// Problem constants (fixed dataset: GraphConvSparse)
#define MAX_NODES 100000
#define MAX_EDGES 3200000
#define IN_DIM    512
#define OUT_DIM   128

// ---------------- scratch (static device globals; no cudaMalloc allowed) ----
__device__ float4 g_xp4[MAX_NODES * (OUT_DIM / 4)];   // projected features [N,128], 51.2 MB
__device__ int    g_rowptr[MAX_NODES + 1];
__device__ int    g_cursor[MAX_NODES];
__device__ int    g_ecol[MAX_EDGES];
__device__ float  g_eval[MAX_EDGES];
// W split into bf16 hi/lo, transposed to [n][k] (k contiguous) for mma B operand
__device__ __nv_bfloat16 g_wt_hi[OUT_DIM * IN_DIM];
__device__ __nv_bfloat16 g_wt_lo[OUT_DIM * IN_DIM];

__device__ __forceinline__ uint32_t smem_u32(const void* p) {
    uint32_t a;
    asm("{ .reg .u64 t; cvta.to.shared.u64 t, %1; cvt.u32.u64 %0, t; }"
        : "=r"(a) : "l"(p));
    return a;
}
__device__ __forceinline__ uint32_t pack_bf16x2(float a, float b) {
    __nv_bfloat162 t = __floats2bfloat162_rn(a, b);   // low half = a, high half = b
    return *reinterpret_cast<uint32_t*>(&t);
}
__device__ __forceinline__ void ldsm_x4(uint32_t& r0, uint32_t& r1,
                                        uint32_t& r2, uint32_t& r3, uint32_t addr) {
    asm volatile("ldmatrix.sync.aligned.m8n8.x4.shared.b16 {%0,%1,%2,%3}, [%4];"
                 : "=r"(r0), "=r"(r1), "=r"(r2), "=r"(r3) : "r"(addr));
}
__device__ __forceinline__ void mma16816(float* d, const uint32_t* a,
                                         const uint32_t* b) {
    asm volatile(
        "mma.sync.aligned.m16n8k16.row.col.f32.bf16.bf16.f32 "
        "{%0,%1,%2,%3}, {%4,%5,%6,%7}, {%8,%9}, {%0,%1,%2,%3};"
        : "+f"(d[0]), "+f"(d[1]), "+f"(d[2]), "+f"(d[3])
        : "r"(a[0]), "r"(a[1]), "r"(a[2]), "r"(a[3]), "r"(b[0]), "r"(b[1]));
}

// ---------------- CSR build ------------------------------------------------
__global__ void k_zero_deg(int n) {
    int i = blockIdx.x * blockDim.x + threadIdx.x;
    if (i < n) g_cursor[i] = 0;
}

__global__ void k_count(const int* __restrict__ erow, int E) {
    int e = blockIdx.x * blockDim.x + threadIdx.x;
    if (e < E) atomicAdd(&g_cursor[__ldcs(erow + e)], 1);
}

// single-block exclusive scan: g_cursor (degrees) -> g_rowptr AND g_cursor
__global__ void k_scan(int n) {
    __shared__ int warpsums[32];
    __shared__ int s_running;
    __shared__ int s_total;
    int tid  = threadIdx.x;           // 1024 threads
    int lane = tid & 31;
    int wid  = tid >> 5;
    if (tid == 0) s_running = 0;
    __syncthreads();
    for (int base = 0; base < n; base += 1024) {
        int i = base + tid;
        int v = (i < n) ? g_cursor[i] : 0;
        int s = v;
        #pragma unroll
        for (int off = 1; off < 32; off <<= 1) {
            int t = __shfl_up_sync(0xffffffffu, s, off);
            if (lane >= off) s += t;
        }
        if (lane == 31) warpsums[wid] = s;
        __syncthreads();
        if (wid == 0) {
            int ws   = warpsums[lane];
            int incl = ws;
            #pragma unroll
            for (int off = 1; off < 32; off <<= 1) {
                int t = __shfl_up_sync(0xffffffffu, incl, off);
                if (lane >= off) incl += t;
            }
            warpsums[lane] = incl - ws;          // exclusive prefix of warp sums
            if (lane == 31) s_total = incl;      // chunk total
        }
        __syncthreads();
        int excl = (s - v) + warpsums[wid] + s_running;
        if (i < n) { g_rowptr[i] = excl; g_cursor[i] = excl; }
        __syncthreads();
        if (tid == 0) s_running += s_total;
        __syncthreads();
    }
    if (tid == 0) g_rowptr[n] = s_running;
}

__global__ void k_scatter(const int* __restrict__ erow, const int* __restrict__ ecol,
                          const float* __restrict__ eval, int E) {
    int e = blockIdx.x * blockDim.x + threadIdx.x;
    if (e < E) {
        int r = erow[e];
        int p = atomicAdd(&g_cursor[r], 1);
        g_ecol[p] = ecol[e];
        g_eval[p] = eval[e];
    }
}

// ---------------- W split: fp32 [k][n] -> bf16 hi/lo transposed [n][k] ------
__global__ void k_wsplit(const float* __restrict__ W) {
    int idx = blockIdx.x * blockDim.x + threadIdx.x;
    if (idx < IN_DIM * OUT_DIM) {
        int k = idx >> 7;            // 0..511
        int n = idx & 127;           // 0..127
        float w = W[(size_t)k * OUT_DIM + n];
        __nv_bfloat16 hi = __float2bfloat16(w);
        float lof = w - __bfloat162float(hi);
        __nv_bfloat16 lo = __float2bfloat16(lof);
        g_wt_hi[(size_t)n * IN_DIM + k] = hi;
        g_wt_lo[(size_t)n * IN_DIM + k] = lo;
    }
}

// ---------------- tensor-core GEMM via mma.sync (bf16-split, fp32 acc) ------
// CTA: 128 rows x 128 cols; K chunks of 32. 512 threads = 16 warps (4x4 grid),
// each warp 32x32 (2 m-tiles x 4 n-tiles of m16n8k16).
// fp32 = hi + lo (bf16); D += Ahi*Bhi + Ahi*Blo + Alo*Bhi  (lo*lo dropped, ~2^-16)
#define KC   32
#define NCHK (IN_DIM / KC)     // 16
#define AST  40                // smem row stride in bf16 (32 data + 8 pad)

__global__ __launch_bounds__(512, 1)
void k_gemm_mma(const float* __restrict__ X, int N) {
    __shared__ __align__(16) __nv_bfloat16 sA[2][128 * AST];  // [hi/lo][row][k]
    __shared__ __align__(16) __nv_bfloat16 sB[2][128 * AST];  // [hi/lo][n][k]

    int tid  = threadIdx.x;
    int wid  = tid >> 5;
    int lane = tid & 31;
    int wm   = wid >> 2;        // warp row 0..3  -> rows wm*32..+31
    int wn   = wid & 3;         // warp col 0..3  -> cols wn*32..+31
    int blockRow = blockIdx.x * 128;
    float* XP = (float*)g_xp4;

    // staging coordinates (fixed per thread)
    int sr = tid >> 2;          // 0..127 (row for A, n for B)
    int sc = (tid & 3) * 8;     // k offset 0/8/16/24

    uint32_t sA0 = smem_u32(sA[0]), sA1 = smem_u32(sA[1]);
    uint32_t sB0 = smem_u32(sB[0]), sB1 = smem_u32(sB[1]);

    // ldmatrix lane-address components
    uint32_t aRow  = lane & 15;
    uint32_t aKoff = (lane & 16) ? 8u : 0u;
    uint32_t bRow  = (lane & 7) + ((lane & 16) ? 8u : 0u);
    uint32_t bKoff = (lane & 8) ? 8u : 0u;

    float acc[2][4][4];
    #pragma unroll
    for (int mt = 0; mt < 2; ++mt)
        #pragma unroll
        for (int nt = 0; nt < 4; ++nt)
            #pragma unroll
            for (int j = 0; j < 4; ++j) acc[mt][nt][j] = 0.f;

    const __nv_bfloat16* wth = g_wt_hi;
    const __nv_bfloat16* wtl = g_wt_lo;

    // ---- stage chunk 0 ----
    {
        int gr = blockRow + sr;
        float4 v0 = make_float4(0.f,0.f,0.f,0.f), v1 = v0;
        if (gr < N) {
            v0 = __ldcs((const float4*)(X + (size_t)gr * IN_DIM + sc));
            v1 = __ldcs((const float4*)(X + (size_t)gr * IN_DIM + sc + 4));
        }
        uint4 hi, lo;
        hi.x = pack_bf16x2(v0.x, v0.y); hi.y = pack_bf16x2(v0.z, v0.w);
        hi.z = pack_bf16x2(v1.x, v1.y); hi.w = pack_bf16x2(v1.z, v1.w);
        lo.x = pack_bf16x2(v0.x - __bfloat162float(__float2bfloat16(v0.x)),
                           v0.y - __bfloat162float(__float2bfloat16(v0.y)));
        lo.y = pack_bf16x2(v0.z - __bfloat162float(__float2bfloat16(v0.z)),
                           v0.w - __bfloat162float(__float2bfloat16(v0.w)));
        lo.z = pack_bf16x2(v1.x - __bfloat162float(__float2bfloat16(v1.x)),
                           v1.y - __bfloat162float(__float2bfloat16(v1.y)));
        lo.w = pack_bf16x2(v1.z - __bfloat162float(__float2bfloat16(v1.z)),
                           v1.w - __bfloat162float(__float2bfloat16(v1.w)));
        *(uint4*)&sA[0][sr * AST + sc] = hi;
        *(uint4*)&sA[1][sr * AST + sc] = lo;
        uint4 bh = *(const uint4*)(wth + (size_t)sr * IN_DIM + sc);
        uint4 bl = *(const uint4*)(wtl + (size_t)sr * IN_DIM + sc);
        *(uint4*)&sB[0][sr * AST + sc] = bh;
        *(uint4*)&sB[1][sr * AST + sc] = bl;
    }
    __syncthreads();

    for (int c = 0; c < NCHK; ++c) {
        // ---- prefetch chunk c+1 into registers ----
        float4 pv0, pv1; uint4 pbh, pbl;
        if (c + 1 < NCHK) {
            int k0n = (c + 1) * KC;
            int gr = blockRow + sr;
            pv0 = make_float4(0.f,0.f,0.f,0.f); pv1 = pv0;
            if (gr < N) {
                pv0 = __ldcs((const float4*)(X + (size_t)gr * IN_DIM + k0n + sc));
                pv1 = __ldcs((const float4*)(X + (size_t)gr * IN_DIM + k0n + sc + 4));
            }
            pbh = *(const uint4*)(wth + (size_t)sr * IN_DIM + k0n + sc);
            pbl = *(const uint4*)(wtl + (size_t)sr * IN_DIM + k0n + sc);
        }

        // ---- compute chunk c: 2 k-steps of 16 ----
        #pragma unroll
        for (int ks = 0; ks < 2; ++ks) {
            uint32_t kbase = (uint32_t)ks * 16;
            uint32_t ah[2][4], al[2][4];
            #pragma unroll
            for (int mt = 0; mt < 2; ++mt) {
                uint32_t off = (((uint32_t)(wm * 32 + mt * 16) + aRow) * AST
                                + kbase + aKoff) * 2;
                ldsm_x4(ah[mt][0], ah[mt][1], ah[mt][2], ah[mt][3], sA0 + off);
                ldsm_x4(al[mt][0], al[mt][1], al[mt][2], al[mt][3], sA1 + off);
            }
            uint32_t bh[4][2], bl[4][2];
            #pragma unroll
            for (int ntp = 0; ntp < 2; ++ntp) {
                uint32_t off = (((uint32_t)(wn * 32 + ntp * 16) + bRow) * AST
                                + kbase + bKoff) * 2;
                ldsm_x4(bh[2*ntp][0], bh[2*ntp][1], bh[2*ntp+1][0], bh[2*ntp+1][1],
                        sB0 + off);
                ldsm_x4(bl[2*ntp][0], bl[2*ntp][1], bl[2*ntp+1][0], bl[2*ntp+1][1],
                        sB1 + off);
            }
            #pragma unroll
            for (int mt = 0; mt < 2; ++mt)
                #pragma unroll
                for (int nt = 0; nt < 4; ++nt) {
                    mma16816(acc[mt][nt], ah[mt], bh[nt]);
                    mma16816(acc[mt][nt], ah[mt], bl[nt]);
                    mma16816(acc[mt][nt], al[mt], bh[nt]);
                }
        }
        __syncthreads();   // everyone done reading smem chunk c

        // ---- store prefetched chunk c+1 into smem ----
        if (c + 1 < NCHK) {
            uint4 hi, lo;
            hi.x = pack_bf16x2(pv0.x, pv0.y); hi.y = pack_bf16x2(pv0.z, pv0.w);
            hi.z = pack_bf16x2(pv1.x, pv1.y); hi.w = pack_bf16x2(pv1.z, pv1.w);
            lo.x = pack_bf16x2(pv0.x - __bfloat162float(__float2bfloat16(pv0.x)),
                               pv0.y - __bfloat162float(__float2bfloat16(pv0.y)));
            lo.y = pack_bf16x2(pv0.z - __bfloat162float(__float2bfloat16(pv0.z)),
                               pv0.w - __bfloat162float(__float2bfloat16(pv0.w)));
            lo.z = pack_bf16x2(pv1.x - __bfloat162float(__float2bfloat16(pv1.x)),
                               pv1.y - __bfloat162float(__float2bfloat16(pv1.y)));
            lo.w = pack_bf16x2(pv1.z - __bfloat162float(__float2bfloat16(pv1.z)),
                               pv1.w - __bfloat162float(__float2bfloat16(pv1.w)));
            *(uint4*)&sA[0][sr * AST + sc] = hi;
            *(uint4*)&sA[1][sr * AST + sc] = lo;
            *(uint4*)&sB[0][sr * AST + sc] = pbh;
            *(uint4*)&sB[1][sr * AST + sc] = pbl;
            __syncthreads();
        }
    }

    // ---- epilogue: write 32x32 per warp to XP ----
    #pragma unroll
    for (int mt = 0; mt < 2; ++mt) {
        int r0 = blockRow + wm * 32 + mt * 16 + (lane >> 2);
        int r1 = r0 + 8;
        #pragma unroll
        for (int nt = 0; nt < 4; ++nt) {
            int cb = wn * 32 + nt * 8 + 2 * (lane & 3);
            if (r0 < N) {
                float2 v = make_float2(acc[mt][nt][0], acc[mt][nt][1]);
                *(float2*)(XP + (size_t)r0 * OUT_DIM + cb) = v;
            }
            if (r1 < N) {
                float2 v = make_float2(acc[mt][nt][2], acc[mt][nt][3]);
                *(float2*)(XP + (size_t)r1 * OUT_DIM + cb) = v;
            }
        }
    }
}

// ---------------- aggregation: one warp per row, fused ReLU -----------------
// Depth-2 software pipeline; edge arrays read with streaming hints (read-once),
// output stored with streaming hints (write-once) so L2 stays owned by g_xp4.
__global__ __launch_bounds__(256)
void k_agg(float* __restrict__ out, int n) {
    int w    = (blockIdx.x * blockDim.x + threadIdx.x) >> 5;
    int lane = threadIdx.x & 31;
    if (w >= n) return;
    int s = g_rowptr[w];
    int e = g_rowptr[w + 1];
    float4 acc = make_float4(0.f, 0.f, 0.f, 0.f);
    const float4* __restrict__ xp4 = g_xp4;

    if (s < e) {
        int   c0 = __ldcs(g_ecol + s);
        float v0 = __ldcs(g_eval + s);
        float4 m0 = xp4[(size_t)c0 * 32 + lane];
        for (int i = s + 1; i < e; ++i) {
            int   c1 = __ldcs(g_ecol + i);
            float v1 = __ldcs(g_eval + i);
            float4 m1 = xp4[(size_t)c1 * 32 + lane];   // issue before consuming m0
            acc.x = fmaf(v0, m0.x, acc.x);
            acc.y = fmaf(v0, m0.y, acc.y);
            acc.z = fmaf(v0, m0.z, acc.z);
            acc.w = fmaf(v0, m0.w, acc.w);
            v0 = v1; m0 = m1;
        }
        acc.x = fmaf(v0, m0.x, acc.x);
        acc.y = fmaf(v0, m0.y, acc.y);
        acc.z = fmaf(v0, m0.z, acc.z);
        acc.w = fmaf(v0, m0.w, acc.w);
    }
    acc.x = fmaxf(acc.x, 0.f);
    acc.y = fmaxf(acc.y, 0.f);
    acc.z = fmaxf(acc.z, 0.f);
    acc.w = fmaxf(acc.w, 0.f);
    __stcs((float4*)out + (size_t)w * 32 + lane, acc);
}

// ---------------- launch ----------------------------------------------------
extern "C" void kernel_launch(void* const* d_in, const int* in_sizes, int n_in,
                              void* d_out, int out_size) {
    const float* x    = (const float*)d_in[0];
    const float* W    = (const float*)d_in[1];
    const int*   erow = (const int*)  d_in[2];
    const int*   ecol = (const int*)  d_in[3];
    const float* eval = (const float*)d_in[4];
    float* out = (float*)d_out;

    int N = in_sizes[0] / IN_DIM;   // 100000
    int E = in_sizes[2];            // 3200000

    int tb = 256;
    // CSR build
    k_zero_deg <<<(N + tb - 1) / tb, tb>>>(N);
    k_count    <<<(E + tb - 1) / tb, tb>>>(erow, E);
    k_scan     <<<1, 1024>>>(N);                    // writes rowptr + cursor
    k_scatter  <<<(E + tb - 1) / tb, tb>>>(erow, ecol, eval, E);
    // dense projection via mma.sync tensor cores (bf16-split fp32)
    k_wsplit   <<<(IN_DIM * OUT_DIM + tb - 1) / tb, tb>>>(W);
    k_gemm_mma <<<(N + 127) / 128, 512>>>(x, N);
    // per-row aggregation + ReLU
    k_agg      <<<(N * 32 + tb - 1) / tb, tb>>>(out, N);
}

// round 14
// speedup vs baseline: 1.8931x; 1.3510x over previous
#include <cuda_runtime.h>
#include <cuda_bf16.h>
#include <stdint.h>

// Problem constants (fixed dataset: GraphConvSparse)
#define MAX_NODES 100000
#define MAX_EDGES 3200000
#define IN_DIM    512
#define OUT_DIM   128

// ---------------- scratch (static device globals; no cudaMalloc allowed) ----
__device__ float4 g_xp4[MAX_NODES * (OUT_DIM / 4)];   // projected features [N,128], 51.2 MB
__device__ int    g_rowptr[MAX_NODES + 1];
__device__ int    g_cursor[MAX_NODES];
__device__ int2   g_epack[MAX_EDGES];                 // packed (col, val-bits) per edge
// W split into bf16 hi/lo, transposed to [n][k] (k contiguous) for mma B operand
__device__ __nv_bfloat16 g_wt_hi[OUT_DIM * IN_DIM];
__device__ __nv_bfloat16 g_wt_lo[OUT_DIM * IN_DIM];

__device__ __forceinline__ uint32_t smem_u32(const void* p) {
    uint32_t a;
    asm("{ .reg .u64 t; cvta.to.shared.u64 t, %1; cvt.u32.u64 %0, t; }"
        : "=r"(a) : "l"(p));
    return a;
}
__device__ __forceinline__ uint32_t pack_bf16x2(float a, float b) {
    __nv_bfloat162 t = __floats2bfloat162_rn(a, b);   // low half = a, high half = b
    return *reinterpret_cast<uint32_t*>(&t);
}
__device__ __forceinline__ void ldsm_x4(uint32_t& r0, uint32_t& r1,
                                        uint32_t& r2, uint32_t& r3, uint32_t addr) {
    asm volatile("ldmatrix.sync.aligned.m8n8.x4.shared.b16 {%0,%1,%2,%3}, [%4];"
                 : "=r"(r0), "=r"(r1), "=r"(r2), "=r"(r3) : "r"(addr));
}
__device__ __forceinline__ void mma16816(float* d, const uint32_t* a,
                                         const uint32_t* b) {
    asm volatile(
        "mma.sync.aligned.m16n8k16.row.col.f32.bf16.bf16.f32 "
        "{%0,%1,%2,%3}, {%4,%5,%6,%7}, {%8,%9}, {%0,%1,%2,%3};"
        : "+f"(d[0]), "+f"(d[1]), "+f"(d[2]), "+f"(d[3])
        : "r"(a[0]), "r"(a[1]), "r"(a[2]), "r"(a[3]), "r"(b[0]), "r"(b[1]));
}

// ---------------- CSR build ------------------------------------------------
__global__ void k_zero_deg(int n) {
    int i = blockIdx.x * blockDim.x + threadIdx.x;
    if (i < n) g_cursor[i] = 0;
}

__global__ void k_count(const int* __restrict__ erow, int E) {
    int e = blockIdx.x * blockDim.x + threadIdx.x;
    if (e < E) atomicAdd(&g_cursor[__ldcs(erow + e)], 1);
}

// single-block exclusive scan: g_cursor (degrees) -> g_rowptr AND g_cursor
__global__ void k_scan(int n) {
    __shared__ int warpsums[32];
    __shared__ int s_running;
    __shared__ int s_total;
    int tid  = threadIdx.x;           // 1024 threads
    int lane = tid & 31;
    int wid  = tid >> 5;
    if (tid == 0) s_running = 0;
    __syncthreads();
    for (int base = 0; base < n; base += 1024) {
        int i = base + tid;
        int v = (i < n) ? g_cursor[i] : 0;
        int s = v;
        #pragma unroll
        for (int off = 1; off < 32; off <<= 1) {
            int t = __shfl_up_sync(0xffffffffu, s, off);
            if (lane >= off) s += t;
        }
        if (lane == 31) warpsums[wid] = s;
        __syncthreads();
        if (wid == 0) {
            int ws   = warpsums[lane];
            int incl = ws;
            #pragma unroll
            for (int off = 1; off < 32; off <<= 1) {
                int t = __shfl_up_sync(0xffffffffu, incl, off);
                if (lane >= off) incl += t;
            }
            warpsums[lane] = incl - ws;          // exclusive prefix of warp sums
            if (lane == 31) s_total = incl;      // chunk total
        }
        __syncthreads();
        int excl = (s - v) + warpsums[wid] + s_running;
        if (i < n) { g_rowptr[i] = excl; g_cursor[i] = excl; }
        __syncthreads();
        if (tid == 0) s_running += s_total;
        __syncthreads();
    }
    if (tid == 0) g_rowptr[n] = s_running;
}

__global__ void k_scatter(const int* __restrict__ erow, const int* __restrict__ ecol,
                          const float* __restrict__ eval, int E) {
    int e = blockIdx.x * blockDim.x + threadIdx.x;
    if (e < E) {
        int r = erow[e];
        int p = atomicAdd(&g_cursor[r], 1);
        g_epack[p] = make_int2(ecol[e], __float_as_int(eval[e]));  // one 8B store
    }
}

// ---------------- W split: fp32 [k][n] -> bf16 hi/lo transposed [n][k] ------
__global__ void k_wsplit(const float* __restrict__ W) {
    int idx = blockIdx.x * blockDim.x + threadIdx.x;
    if (idx < IN_DIM * OUT_DIM) {
        int k = idx >> 7;            // 0..511
        int n = idx & 127;           // 0..127
        float w = W[(size_t)k * OUT_DIM + n];
        __nv_bfloat16 hi = __float2bfloat16(w);
        float lof = w - __bfloat162float(hi);
        __nv_bfloat16 lo = __float2bfloat16(lof);
        g_wt_hi[(size_t)n * IN_DIM + k] = hi;
        g_wt_lo[(size_t)n * IN_DIM + k] = lo;
    }
}

// ---------------- tensor-core GEMM via mma.sync (bf16-split, fp32 acc) ------
// CTA: 128 rows x 128 cols; K chunks of 32. 512 threads = 16 warps (4x4 grid),
// each warp 32x32 (2 m-tiles x 4 n-tiles of m16n8k16).
// fp32 = hi + lo (bf16); D += Ahi*Bhi + Ahi*Blo + Alo*Bhi  (lo*lo dropped, ~2^-16)
#define KC   32
#define NCHK (IN_DIM / KC)     // 16
#define AST  40                // smem row stride in bf16 (32 data + 8 pad)

__global__ __launch_bounds__(512, 1)
void k_gemm_mma(const float* __restrict__ X, int N) {
    __shared__ __align__(16) __nv_bfloat16 sA[2][128 * AST];  // [hi/lo][row][k]
    __shared__ __align__(16) __nv_bfloat16 sB[2][128 * AST];  // [hi/lo][n][k]

    int tid  = threadIdx.x;
    int wid  = tid >> 5;
    int lane = tid & 31;
    int wm   = wid >> 2;        // warp row 0..3  -> rows wm*32..+31
    int wn   = wid & 3;         // warp col 0..3  -> cols wn*32..+31
    int blockRow = blockIdx.x * 128;
    float* XP = (float*)g_xp4;

    // staging coordinates (fixed per thread)
    int sr = tid >> 2;          // 0..127 (row for A, n for B)
    int sc = (tid & 3) * 8;     // k offset 0/8/16/24

    uint32_t sA0 = smem_u32(sA[0]), sA1 = smem_u32(sA[1]);
    uint32_t sB0 = smem_u32(sB[0]), sB1 = smem_u32(sB[1]);

    // ldmatrix lane-address components
    uint32_t aRow  = lane & 15;
    uint32_t aKoff = (lane & 16) ? 8u : 0u;
    uint32_t bRow  = (lane & 7) + ((lane & 16) ? 8u : 0u);
    uint32_t bKoff = (lane & 8) ? 8u : 0u;

    float acc[2][4][4];
    #pragma unroll
    for (int mt = 0; mt < 2; ++mt)
        #pragma unroll
        for (int nt = 0; nt < 4; ++nt)
            #pragma unroll
            for (int j = 0; j < 4; ++j) acc[mt][nt][j] = 0.f;

    const __nv_bfloat16* wth = g_wt_hi;
    const __nv_bfloat16* wtl = g_wt_lo;

    // ---- stage chunk 0 ----
    {
        int gr = blockRow + sr;
        float4 v0 = make_float4(0.f,0.f,0.f,0.f), v1 = v0;
        if (gr < N) {
            v0 = __ldcs((const float4*)(X + (size_t)gr * IN_DIM + sc));
            v1 = __ldcs((const float4*)(X + (size_t)gr * IN_DIM + sc + 4));
        }
        uint4 hi, lo;
        hi.x = pack_bf16x2(v0.x, v0.y); hi.y = pack_bf16x2(v0.z, v0.w);
        hi.z = pack_bf16x2(v1.x, v1.y); hi.w = pack_bf16x2(v1.z, v1.w);
        lo.x = pack_bf16x2(v0.x - __bfloat162float(__float2bfloat16(v0.x)),
                           v0.y - __bfloat162float(__float2bfloat16(v0.y)));
        lo.y = pack_bf16x2(v0.z - __bfloat162float(__float2bfloat16(v0.z)),
                           v0.w - __bfloat162float(__float2bfloat16(v0.w)));
        lo.z = pack_bf16x2(v1.x - __bfloat162float(__float2bfloat16(v1.x)),
                           v1.y - __bfloat162float(__float2bfloat16(v1.y)));
        lo.w = pack_bf16x2(v1.z - __bfloat162float(__float2bfloat16(v1.z)),
                           v1.w - __bfloat162float(__float2bfloat16(v1.w)));
        *(uint4*)&sA[0][sr * AST + sc] = hi;
        *(uint4*)&sA[1][sr * AST + sc] = lo;
        uint4 bh = *(const uint4*)(wth + (size_t)sr * IN_DIM + sc);
        uint4 bl = *(const uint4*)(wtl + (size_t)sr * IN_DIM + sc);
        *(uint4*)&sB[0][sr * AST + sc] = bh;
        *(uint4*)&sB[1][sr * AST + sc] = bl;
    }
    __syncthreads();

    for (int c = 0; c < NCHK; ++c) {
        // ---- prefetch chunk c+1 into registers ----
        float4 pv0, pv1; uint4 pbh, pbl;
        if (c + 1 < NCHK) {
            int k0n = (c + 1) * KC;
            int gr = blockRow + sr;
            pv0 = make_float4(0.f,0.f,0.f,0.f); pv1 = pv0;
            if (gr < N) {
                pv0 = __ldcs((const float4*)(X + (size_t)gr * IN_DIM + k0n + sc));
                pv1 = __ldcs((const float4*)(X + (size_t)gr * IN_DIM + k0n + sc + 4));
            }
            pbh = *(const uint4*)(wth + (size_t)sr * IN_DIM + k0n + sc);
            pbl = *(const uint4*)(wtl + (size_t)sr * IN_DIM + k0n + sc);
        }

        // ---- compute chunk c: 2 k-steps of 16 ----
        #pragma unroll
        for (int ks = 0; ks < 2; ++ks) {
            uint32_t kbase = (uint32_t)ks * 16;
            uint32_t ah[2][4], al[2][4];
            #pragma unroll
            for (int mt = 0; mt < 2; ++mt) {
                uint32_t off = (((uint32_t)(wm * 32 + mt * 16) + aRow) * AST
                                + kbase + aKoff) * 2;
                ldsm_x4(ah[mt][0], ah[mt][1], ah[mt][2], ah[mt][3], sA0 + off);
                ldsm_x4(al[mt][0], al[mt][1], al[mt][2], al[mt][3], sA1 + off);
            }
            uint32_t bh[4][2], bl[4][2];
            #pragma unroll
            for (int ntp = 0; ntp < 2; ++ntp) {
                uint32_t off = (((uint32_t)(wn * 32 + ntp * 16) + bRow) * AST
                                + kbase + bKoff) * 2;
                ldsm_x4(bh[2*ntp][0], bh[2*ntp][1], bh[2*ntp+1][0], bh[2*ntp+1][1],
                        sB0 + off);
                ldsm_x4(bl[2*ntp][0], bl[2*ntp][1], bl[2*ntp+1][0], bl[2*ntp+1][1],
                        sB1 + off);
            }
            #pragma unroll
            for (int mt = 0; mt < 2; ++mt)
                #pragma unroll
                for (int nt = 0; nt < 4; ++nt) {
                    mma16816(acc[mt][nt], ah[mt], bh[nt]);
                    mma16816(acc[mt][nt], ah[mt], bl[nt]);
                    mma16816(acc[mt][nt], al[mt], bh[nt]);
                }
        }
        __syncthreads();   // everyone done reading smem chunk c

        // ---- store prefetched chunk c+1 into smem ----
        if (c + 1 < NCHK) {
            uint4 hi, lo;
            hi.x = pack_bf16x2(pv0.x, pv0.y); hi.y = pack_bf16x2(pv0.z, pv0.w);
            hi.z = pack_bf16x2(pv1.x, pv1.y); hi.w = pack_bf16x2(pv1.z, pv1.w);
            lo.x = pack_bf16x2(pv0.x - __bfloat162float(__float2bfloat16(pv0.x)),
                               pv0.y - __bfloat162float(__float2bfloat16(pv0.y)));
            lo.y = pack_bf16x2(pv0.z - __bfloat162float(__float2bfloat16(pv0.z)),
                               pv0.w - __bfloat162float(__float2bfloat16(pv0.w)));
            lo.z = pack_bf16x2(pv1.x - __bfloat162float(__float2bfloat16(pv1.x)),
                               pv1.y - __bfloat162float(__float2bfloat16(pv1.y)));
            lo.w = pack_bf16x2(pv1.z - __bfloat162float(__float2bfloat16(pv1.z)),
                               pv1.w - __bfloat162float(__float2bfloat16(pv1.w)));
            *(uint4*)&sA[0][sr * AST + sc] = hi;
            *(uint4*)&sA[1][sr * AST + sc] = lo;
            *(uint4*)&sB[0][sr * AST + sc] = pbh;
            *(uint4*)&sB[1][sr * AST + sc] = pbl;
            __syncthreads();
        }
    }

    // ---- epilogue: write 32x32 per warp to XP ----
    #pragma unroll
    for (int mt = 0; mt < 2; ++mt) {
        int r0 = blockRow + wm * 32 + mt * 16 + (lane >> 2);
        int r1 = r0 + 8;
        #pragma unroll
        for (int nt = 0; nt < 4; ++nt) {
            int cb = wn * 32 + nt * 8 + 2 * (lane & 3);
            if (r0 < N) {
                float2 v = make_float2(acc[mt][nt][0], acc[mt][nt][1]);
                *(float2*)(XP + (size_t)r0 * OUT_DIM + cb) = v;
            }
            if (r1 < N) {
                float2 v = make_float2(acc[mt][nt][2], acc[mt][nt][3]);
                *(float2*)(XP + (size_t)r1 * OUT_DIM + cb) = v;
            }
        }
    }
}

// ---------------- aggregation: one warp per row, fused ReLU -----------------
// Depth-2 software pipeline; packed (col,val) read as one 8B streaming load;
// output stored with streaming hints so L2 stays owned by g_xp4.
__global__ __launch_bounds__(256)
void k_agg(float* __restrict__ out, int n) {
    int w    = (blockIdx.x * blockDim.x + threadIdx.x) >> 5;
    int lane = threadIdx.x & 31;
    if (w >= n) return;
    int s = g_rowptr[w];
    int e = g_rowptr[w + 1];
    float4 acc = make_float4(0.f, 0.f, 0.f, 0.f);
    const float4* __restrict__ xp4 = g_xp4;

    if (s < e) {
        int2  p0 = __ldcs(g_epack + s);
        float v0 = __int_as_float(p0.y);
        float4 m0 = xp4[(size_t)p0.x * 32 + lane];
        for (int i = s + 1; i < e; ++i) {
            int2  p1 = __ldcs(g_epack + i);
            float v1 = __int_as_float(p1.y);
            float4 m1 = xp4[(size_t)p1.x * 32 + lane];   // issue before consuming m0
            acc.x = fmaf(v0, m0.x, acc.x);
            acc.y = fmaf(v0, m0.y, acc.y);
            acc.z = fmaf(v0, m0.z, acc.z);
            acc.w = fmaf(v0, m0.w, acc.w);
            v0 = v1; m0 = m1;
        }
        acc.x = fmaf(v0, m0.x, acc.x);
        acc.y = fmaf(v0, m0.y, acc.y);
        acc.z = fmaf(v0, m0.z, acc.z);
        acc.w = fmaf(v0, m0.w, acc.w);
    }
    acc.x = fmaxf(acc.x, 0.f);
    acc.y = fmaxf(acc.y, 0.f);
    acc.z = fmaxf(acc.z, 0.f);
    acc.w = fmaxf(acc.w, 0.f);
    __stcs((float4*)out + (size_t)w * 32 + lane, acc);
}

// ---------------- launch ----------------------------------------------------
extern "C" void kernel_launch(void* const* d_in, const int* in_sizes, int n_in,
                              void* d_out, int out_size) {
    const float* x    = (const float*)d_in[0];
    const float* W    = (const float*)d_in[1];
    const int*   erow = (const int*)  d_in[2];
    const int*   ecol = (const int*)  d_in[3];
    const float* eval = (const float*)d_in[4];
    float* out = (float*)d_out;

    int N = in_sizes[0] / IN_DIM;   // 100000
    int E = in_sizes[2];            // 3200000

    // one-time host-side stream/event objects (not device memory)
    static cudaStream_t s_side = nullptr;
    static cudaEvent_t  ev_fork = nullptr, ev_join = nullptr;
    if (s_side == nullptr) {
        cudaStreamCreateWithFlags(&s_side, cudaStreamNonBlocking);
        cudaEventCreateWithFlags(&ev_fork, cudaEventDisableTiming);
        cudaEventCreateWithFlags(&ev_join, cudaEventDisableTiming);
    }

    int tb = 256;
    // fork: CSR build chain on side stream, GEMM chain on main stream
    cudaEventRecord(ev_fork, 0);
    cudaStreamWaitEvent(s_side, ev_fork, 0);

    k_zero_deg <<<(N + tb - 1) / tb, tb, 0, s_side>>>(N);
    k_count    <<<(E + tb - 1) / tb, tb, 0, s_side>>>(erow, E);
    k_scan     <<<1, 1024, 0, s_side>>>(N);          // writes rowptr + cursor
    k_scatter  <<<(E + tb - 1) / tb, tb, 0, s_side>>>(erow, ecol, eval, E);
    cudaEventRecord(ev_join, s_side);

    k_wsplit   <<<(IN_DIM * OUT_DIM + tb - 1) / tb, tb>>>(W);
    k_gemm_mma <<<(N + 127) / 128, 512>>>(x, N);

    // join: aggregation needs both CSR and projected features
    cudaStreamWaitEvent(0, ev_join, 0);
    k_agg      <<<(N * 32 + tb - 1) / tb, tb>>>(out, N);
}